// round 13
// baseline (speedup 1.0000x reference)
#include <cuda_runtime.h>
#include <cuda_bf16.h>
#include <math.h>

#define Bq 64
#define Nq 4096
#define Dq 256
#define Hq 512
#define ROWS 512
#define SCALEF 0.0625f
#define LN_EPS 1e-5f
#define EPS_A 1e-8f

#define TPW 4
#define TILE_TOK 32
#define ATPB2 8
#define ACH (Nq/(TILE_TOK*ATPB2))   // 16

// -------------------- scratch --------------------
__device__ float g_xln[(size_t)Bq*Nq*Dq];
__device__ float g_slots[ROWS*Dq];
__device__ float g_s[ROWS*Dq];
__device__ float g_qk[ROWS*Dq];
__device__ float g_c[ROWS];
__device__ float g_part[(size_t)ACH*ROWS*Dq];
__device__ float g_dpart[ACH*ROWS];
__device__ float g_w2t[Dq*Dq];
__device__ float g_vb[Dq];
__device__ float g_bqk[Dq];
__device__ float g_cconst[1];

__device__ __forceinline__ float dot4f(float4 a, float4 b) {
    float p = a.x*b.x;
    p = fmaf(a.y, b.y, p);
    p = fmaf(a.z, b.z, p);
    p = fmaf(a.w, b.w, p);
    return p;
}

// -------------------- LayerNorm rows of 256 --------------------
__global__ void ln_rows_kernel(const float* __restrict__ x, const float* __restrict__ w,
                               const float* __restrict__ bb, float* __restrict__ y) {
    __shared__ float sm[8];
    __shared__ float sm2[8];
    size_t row = blockIdx.x;
    int t = threadIdx.x;
    float v = x[row*Dq + t];
    float s = v;
    #pragma unroll
    for (int o = 16; o > 0; o >>= 1) s += __shfl_xor_sync(0xffffffffu, s, o);
    if ((t & 31) == 0) sm[t >> 5] = s;
    __syncthreads();
    float mean = 0.f;
    #pragma unroll
    for (int i = 0; i < 8; i++) mean += sm[i];
    mean *= (1.0f/Dq);
    float d = v - mean;
    float sq = d*d;
    #pragma unroll
    for (int o = 16; o > 0; o >>= 1) sq += __shfl_xor_sync(0xffffffffu, sq, o);
    if ((t & 31) == 0) sm2[t >> 5] = sq;
    __syncthreads();
    float var = 0.f;
    #pragma unroll
    for (int i = 0; i < 8; i++) var += sm2[i];
    var *= (1.0f/Dq);
    y[row*Dq + t] = d * rsqrtf(var + LN_EPS) * w[t] + bb[t];
}

// -------------------- LN(slots) + c (iter-0 prologue piece) --------------------
__global__ void lncv_kernel(const float* __restrict__ x, const float* __restrict__ w,
                            const float* __restrict__ bb, const float* __restrict__ vb,
                            const float* __restrict__ cconst,
                            float* __restrict__ y, float* __restrict__ c) {
    __shared__ float sm[8];
    __shared__ float sm2[8];
    __shared__ float sm3[8];
    size_t row = blockIdx.x;
    int t = threadIdx.x;
    float v = x[row*Dq + t];
    float s = v;
    #pragma unroll
    for (int o = 16; o > 0; o >>= 1) s += __shfl_xor_sync(0xffffffffu, s, o);
    if ((t & 31) == 0) sm[t >> 5] = s;
    __syncthreads();
    float mean = 0.f;
    #pragma unroll
    for (int i = 0; i < 8; i++) mean += sm[i];
    mean *= (1.0f/Dq);
    float d = v - mean;
    float sq = d*d;
    #pragma unroll
    for (int o = 16; o > 0; o >>= 1) sq += __shfl_xor_sync(0xffffffffu, sq, o);
    if ((t & 31) == 0) sm2[t >> 5] = sq;
    __syncthreads();
    float var = 0.f;
    #pragma unroll
    for (int i = 0; i < 8; i++) var += sm2[i];
    var *= (1.0f/Dq);
    float out = d * rsqrtf(var + LN_EPS) * w[t] + bb[t];
    y[row*Dq + t] = out;
    float p = out * vb[t];
    #pragma unroll
    for (int o = 16; o > 0; o >>= 1) p += __shfl_xor_sync(0xffffffffu, p, o);
    if ((t & 31) == 0) sm3[t >> 5] = p;
    __syncthreads();
    if (t == 0) {
        float sum = 0.f;
        #pragma unroll
        for (int i = 0; i < 8; i++) sum += sm3[i];
        c[row] = sum + cconst[0];
    }
}

__global__ void init_slots_kernel(const float* __restrict__ qp, float* __restrict__ slots) {
    int row = blockIdx.x, d = threadIdx.x;
    slots[row*Dq + d] = qp[(row & 7)*Dq + d];
}

// -------------------- precompute W2T = SCALE*(wq.T@wk) [n][k] --------------------
__global__ void __launch_bounds__(256) prep_w2_kernel(const float* __restrict__ wq,
                                                      const float* __restrict__ wk,
                                                      float* __restrict__ w2t) {
    __shared__ float As[64][68];
    __shared__ float Bs[64][68];
    int n0 = blockIdx.y * 64, m0 = blockIdx.x * 64;
    int t = threadIdx.x, tx = t & 15, ty = t >> 4;
    float acc[4][4] = {};
    for (int e0 = 0; e0 < Dq; e0 += 64) {
        #pragma unroll
        for (int i = 0; i < 4; i++) {
            int f4 = t + i*256;
            int r = f4 >> 4, cq = f4 & 15;
            float4 va = *(const float4*)(wq + (size_t)(e0 + r)*Dq + m0 + 4*cq);
            *(float4*)&As[r][4*cq] = va;
            float4 vb4 = *(const float4*)(wk + (size_t)(e0 + r)*Dq + n0 + 4*cq);
            *(float4*)&Bs[r][4*cq] = vb4;
        }
        __syncthreads();
        #pragma unroll
        for (int kk = 0; kk < 64; kk++) {
            float nv[4], mv[4];
            #pragma unroll
            for (int i = 0; i < 4; i++) nv[i] = Bs[kk][4*ty + i];
            #pragma unroll
            for (int j = 0; j < 4; j++) mv[j] = As[kk][4*tx + j];
            #pragma unroll
            for (int i = 0; i < 4; i++)
                #pragma unroll
                for (int j = 0; j < 4; j++)
                    acc[i][j] = fmaf(nv[i], mv[j], acc[i][j]);
        }
        __syncthreads();
    }
    #pragma unroll
    for (int i = 0; i < 4; i++)
        #pragma unroll
        for (int j = 0; j < 4; j++)
            w2t[(size_t)(n0 + 4*ty + i)*Dq + m0 + 4*tx + j] = SCALEF * acc[i][j];
}

// -------------------- precompute vb, bqk, cconst --------------------
__global__ void prep_small2_kernel(const float* __restrict__ wq, const float* __restrict__ wk,
                                   const float* __restrict__ bq, const float* __restrict__ bk,
                                   float* __restrict__ vb, float* __restrict__ bqk,
                                   float* __restrict__ cconst) {
    __shared__ float red[8][33];
    int blk = blockIdx.x;
    int t = threadIdx.x;
    int to = t & 31, eg = t >> 5;
    bool isB = blk >= 8;
    int t0 = (blk & 7)*32 + to;
    float p = 0.f;
    #pragma unroll 4
    for (int e = eg*32; e < eg*32 + 32; e++) {
        p = isB ? fmaf(bq[e], wk[(size_t)e*Dq + t0], p)
                : fmaf(wq[(size_t)e*Dq + t0], bk[e], p);
    }
    red[eg][to] = p;
    __syncthreads();
    if (t < 32) {
        float s = 0.f;
        #pragma unroll
        for (int i = 0; i < 8; i++) s += red[i][t];
        (isB ? bqk : vb)[(blk & 7)*32 + t] = SCALEF * s;
    }
    if (blk == 0) {
        __syncthreads();
        float q = bq[t]*bk[t];
        #pragma unroll
        for (int o = 16; o > 0; o >>= 1) q += __shfl_xor_sync(0xffffffffu, q, o);
        if ((t & 31) == 0) red[0][t >> 5] = q;
        __syncthreads();
        if (t == 0) {
            float s = 0.f;
            #pragma unroll
            for (int i = 0; i < 8; i++) s += red[0][i];
            cconst[0] = SCALEF * s;
        }
    }
}

// -------------------- GEMM (qk prologue only) --------------------
__global__ void __launch_bounds__(256) gemm64_kernel(const float* __restrict__ A,
                                                     const float* __restrict__ W,
                                                     const float* __restrict__ bias,
                                                     float* __restrict__ C,
                                                     int N, int K) {
    __shared__ float As[64][65];
    __shared__ float Bs[64][65];
    int m0 = blockIdx.y*64, n0 = blockIdx.x*64;
    int t = threadIdx.x, tx = t & 15, ty = t >> 4;
    float acc[4][4] = {};
    for (int k0 = 0; k0 < K; k0 += 64) {
        #pragma unroll
        for (int i = 0; i < 4; i++) {
            int f4 = t + i*256;
            int r = f4 >> 4, kq = f4 & 15;
            float4 va = *(const float4*)(A + (size_t)(m0 + r)*K + k0 + 4*kq);
            As[r][4*kq + 0] = va.x; As[r][4*kq + 1] = va.y;
            As[r][4*kq + 2] = va.z; As[r][4*kq + 3] = va.w;
            float4 vb4 = *(const float4*)(W + (size_t)(n0 + r)*K + k0 + 4*kq);
            Bs[r][4*kq + 0] = vb4.x; Bs[r][4*kq + 1] = vb4.y;
            Bs[r][4*kq + 2] = vb4.z; Bs[r][4*kq + 3] = vb4.w;
        }
        __syncthreads();
        #pragma unroll
        for (int kk = 0; kk < 64; kk++) {
            float a[4], b[4];
            #pragma unroll
            for (int i = 0; i < 4; i++) a[i] = As[4*ty + i][kk];
            #pragma unroll
            for (int j = 0; j < 4; j++) b[j] = Bs[4*tx + j][kk];
            #pragma unroll
            for (int i = 0; i < 4; i++)
                #pragma unroll
                for (int j = 0; j < 4; j++)
                    acc[i][j] = fmaf(a[i], b[j], acc[i][j]);
        }
        __syncthreads();
    }
    #pragma unroll
    for (int i = 0; i < 4; i++) {
        int m = m0 + 4*ty + i;
        #pragma unroll
        for (int j = 0; j < 4; j++) {
            int n = n0 + 4*tx + j;
            C[(size_t)m*N + n] = acc[i][j] + bias[n];
        }
    }
}

// -------------------- attend v3 --------------------
__global__ void __launch_bounds__(256, 1) attend3_kernel(const float* __restrict__ xln,
                                                         const float* __restrict__ qk,
                                                         const float* __restrict__ cc,
                                                         float* __restrict__ part,
                                                         float* __restrict__ dpart) {
    __shared__ float4 qk4[512];
    __shared__ float red[2048];
    __shared__ float sds[64];
    __shared__ float a_sh[8][32];
    int b = blockIdx.y;
    int t = threadIdx.x, w = t >> 5, l = t & 31;
    {
        const float4* src = (const float4*)(qk + (size_t)b*8*Dq);
        qk4[t]       = src[t];
        qk4[t + 256] = src[t + 256];
    }
    float cr = cc[b*8 + (l & 7)];
    #pragma unroll
    for (int i = 0; i < 8; i++) red[t + i*256] = 0.f;
    __syncthreads();

    float accB[64];
    #pragma unroll
    for (int i = 0; i < 64; i++) accB[i] = 0.f;
    float dsl = 0.f;

    const float* xp0 = xln + ((size_t)b*Nq + (size_t)blockIdx.x*(TILE_TOK*ATPB2) + w*TPW)*Dq;

    for (int tile = 0; tile < ATPB2; tile++) {
        const float* xp = xp0 + (size_t)tile*TILE_TOK*Dq;
        float4 xa[TPW], xb[TPW];
        #pragma unroll
        for (int j = 0; j < TPW; j++) {
            xa[j] = *(const float4*)(xp + j*Dq + 4*l);
            xb[j] = *(const float4*)(xp + j*Dq + 128 + 4*l);
        }
        float v[32];
        #pragma unroll
        for (int s = 0; s < 8; s++) {
            float4 qa = qk4[s*64 + l];
            float4 qb = qk4[s*64 + 32 + l];
            #pragma unroll
            for (int j = 0; j < TPW; j++) {
                float p = xa[j].x * qa.x;
                p = fmaf(xa[j].y, qa.y, p);
                p = fmaf(xa[j].z, qa.z, p);
                p = fmaf(xa[j].w, qa.w, p);
                p = fmaf(xb[j].x, qb.x, p);
                p = fmaf(xb[j].y, qb.y, p);
                p = fmaf(xb[j].z, qb.z, p);
                p = fmaf(xb[j].w, qb.w, p);
                v[j*8 + s] = p;
            }
        }
        #pragma unroll
        for (int half = 16; half >= 1; half >>= 1) {
            int hi = l & half;
            #pragma unroll
            for (int i = 0; i < half; i++) {
                float send = hi ? v[i] : v[i + half];
                float keep = hi ? v[i + half] : v[i];
                v[i] = keep + __shfl_xor_sync(0xffffffffu, send, half);
            }
        }
        float lg = v[0] + cr;
        float m = lg;
        #pragma unroll
        for (int o = 1; o <= 4; o <<= 1) m = fmaxf(m, __shfl_xor_sync(0xffffffffu, m, o));
        float e = __expf(lg - m);
        float sum = e;
        #pragma unroll
        for (int o = 1; o <= 4; o <<= 1) sum += __shfl_xor_sync(0xffffffffu, sum, o);
        float a = fmaf(e, __fdividef(1.f, sum), EPS_A);
        dsl += a;
        __syncwarp();
        a_sh[w][l] = a;
        __syncwarp();
        #pragma unroll
        for (int j = 0; j < TPW; j++) {
            float4 a0 = *(const float4*)&a_sh[w][j*8];
            float4 a1 = *(const float4*)&a_sh[w][j*8 + 4];
            float av[8] = {a0.x, a0.y, a0.z, a0.w, a1.x, a1.y, a1.z, a1.w};
            #pragma unroll
            for (int s = 0; s < 8; s++) {
                accB[s*8 + 0] = fmaf(av[s], xa[j].x, accB[s*8 + 0]);
                accB[s*8 + 1] = fmaf(av[s], xa[j].y, accB[s*8 + 1]);
                accB[s*8 + 2] = fmaf(av[s], xa[j].z, accB[s*8 + 2]);
                accB[s*8 + 3] = fmaf(av[s], xa[j].w, accB[s*8 + 3]);
                accB[s*8 + 4] = fmaf(av[s], xb[j].x, accB[s*8 + 4]);
                accB[s*8 + 5] = fmaf(av[s], xb[j].y, accB[s*8 + 5]);
                accB[s*8 + 6] = fmaf(av[s], xb[j].z, accB[s*8 + 6]);
                accB[s*8 + 7] = fmaf(av[s], xb[j].w, accB[s*8 + 7]);
            }
        }
    }
    dsl += __shfl_xor_sync(0xffffffffu, dsl, 8);
    dsl += __shfl_xor_sync(0xffffffffu, dsl, 16);
    if (l < 8) sds[w*8 + l] = dsl;
    for (int r = 0; r < 8; r++) {
        __syncthreads();
        if (w == r) {
            #pragma unroll
            for (int s = 0; s < 8; s++) {
                #pragma unroll
                for (int q = 0; q < 4; q++) {
                    red[s*256 + 4*l + q]       += accB[s*8 + q];
                    red[s*256 + 128 + 4*l + q] += accB[s*8 + 4 + q];
                }
            }
        }
    }
    __syncthreads();
    size_t pbase = ((size_t)blockIdx.x*ROWS + b*8)*Dq;
    #pragma unroll
    for (int i = 0; i < 8; i++) part[pbase + i*256 + t] = red[i*256 + t];
    if (t < 8) {
        float sum = 0.f;
        #pragma unroll
        for (int ww = 0; ww < 8; ww++) sum += sds[ww*8 + t];
        dpart[blockIdx.x*ROWS + b*8 + t] = sum;
    }
}

// -------------------- fused per-iteration epilogue --------------------
__global__ void __launch_bounds__(256) epilogue_kernel(
    const float* __restrict__ part, const float* __restrict__ dpart,
    float* __restrict__ slots,
    const float* __restrict__ wv,   const float* __restrict__ bv,
    const float* __restrict__ w_ih, const float* __restrict__ b_ih,
    const float* __restrict__ w_hh, const float* __restrict__ b_hh,
    const float* __restrict__ w1,   const float* __restrict__ b1,
    const float* __restrict__ w2,   const float* __restrict__ b2,
    const float* __restrict__ lfw,  const float* __restrict__ lfb,
    const float* __restrict__ lsw,  const float* __restrict__ lsb,
    const float* __restrict__ vb,   const float* __restrict__ cconst,
    const float* __restrict__ w2t,  const float* __restrict__ bqk,
    float* __restrict__ qk_out, float* __restrict__ c_out,
    float* __restrict__ final_out, int last)
{
    __shared__ __align__(16) float sl[4][256];
    __shared__ __align__(16) float nm[4][256];
    __shared__ __align__(16) float up[4][256];
    __shared__ __align__(16) float hl[4][256];
    __shared__ __align__(16) float f1[4][512];
    __shared__ float dred[4];
    __shared__ float rb[4][8];
    int t = threadIdx.x, l = t & 31, w = t >> 5;
    int r0 = blockIdx.x * 4;

    #pragma unroll
    for (int r = 0; r < 4; r++)
        sl[r][t] = slots[(size_t)(r0 + r)*Dq + t];
    if (t < 4) {
        float dn = 0.f;
        #pragma unroll
        for (int ch = 0; ch < ACH; ch++) dn += dpart[ch*ROWS + r0 + t];
        dred[t] = dn;
    }
    #pragma unroll
    for (int r = 0; r < 4; r++) {
        float s = 0.f;
        #pragma unroll
        for (int ch = 0; ch < ACH; ch++)
            s += part[((size_t)ch*ROWS + r0 + r)*Dq + t];
        nm[r][t] = s;
    }
    __syncthreads();

    {
        float a0 = 0.f, a1 = 0.f, a2 = 0.f, a3 = 0.f;
        const float4* wr = (const float4*)(wv + (size_t)t*Dq);
        #pragma unroll 8
        for (int k4 = 0; k4 < 64; k4++) {
            float4 wv4 = wr[k4];
            a0 += dot4f(wv4, *(const float4*)&nm[0][k4*4]);
            a1 += dot4f(wv4, *(const float4*)&nm[1][k4*4]);
            a2 += dot4f(wv4, *(const float4*)&nm[2][k4*4]);
            a3 += dot4f(wv4, *(const float4*)&nm[3][k4*4]);
        }
        float bvt = bv[t];
        up[0][t] = a0 / dred[0] + bvt;
        up[1][t] = a1 / dred[1] + bvt;
        up[2][t] = a2 / dred[2] + bvt;
        up[3][t] = a3 / dred[3] + bvt;
    }
    __syncthreads();

    float xr[4] = {}, xz[4] = {}, xn[4] = {};
    {
        const float4* wir = (const float4*)(w_ih + (size_t)t*Dq);
        const float4* wiz = (const float4*)(w_ih + (size_t)(256 + t)*Dq);
        const float4* win = (const float4*)(w_ih + (size_t)(512 + t)*Dq);
        #pragma unroll 4
        for (int k4 = 0; k4 < 64; k4++) {
            float4 wr4 = wir[k4], wz4 = wiz[k4], wn4 = win[k4];
            #pragma unroll
            for (int r = 0; r < 4; r++) {
                float4 u = *(const float4*)&up[r][k4*4];
                xr[r] += dot4f(wr4, u);
                xz[r] += dot4f(wz4, u);
                xn[r] += dot4f(wn4, u);
            }
        }
    }
    float hr[4] = {}, hz[4] = {}, hn[4] = {};
    {
        const float4* whr = (const float4*)(w_hh + (size_t)t*Dq);
        const float4* whz = (const float4*)(w_hh + (size_t)(256 + t)*Dq);
        const float4* whn = (const float4*)(w_hh + (size_t)(512 + t)*Dq);
        #pragma unroll 4
        for (int k4 = 0; k4 < 64; k4++) {
            float4 wr4 = whr[k4], wz4 = whz[k4], wn4 = whn[k4];
            #pragma unroll
            for (int r = 0; r < 4; r++) {
                float4 s = *(const float4*)&sl[r][k4*4];
                hr[r] += dot4f(wr4, s);
                hz[r] += dot4f(wz4, s);
                hn[r] += dot4f(wn4, s);
            }
        }
    }
    {
        float bir = b_ih[t], biz = b_ih[256 + t], bin = b_ih[512 + t];
        float bhr = b_hh[t], bhz = b_hh[256 + t], bhn = b_hh[512 + t];
        #pragma unroll
        for (int r = 0; r < 4; r++) {
            float rr = 1.f/(1.f + expf(-(xr[r] + bir + hr[r] + bhr)));
            float zz = 1.f/(1.f + expf(-(xz[r] + biz + hz[r] + bhz)));
            float nn = tanhf(xn[r] + bin + rr*(hn[r] + bhn));
            nm[r][t] = (1.f - zz)*nn + zz*sl[r][t];
        }
    }
    __syncthreads();

    {
        float hv[4], s0, s1, s2, s3;
        #pragma unroll
        for (int r = 0; r < 4; r++) hv[r] = nm[r][t];
        s0 = hv[0]; s1 = hv[1]; s2 = hv[2]; s3 = hv[3];
        #pragma unroll
        for (int o = 16; o > 0; o >>= 1) {
            s0 += __shfl_xor_sync(0xffffffffu, s0, o);
            s1 += __shfl_xor_sync(0xffffffffu, s1, o);
            s2 += __shfl_xor_sync(0xffffffffu, s2, o);
            s3 += __shfl_xor_sync(0xffffffffu, s3, o);
        }
        if (l == 0) { rb[0][w] = s0; rb[1][w] = s1; rb[2][w] = s2; rb[3][w] = s3; }
        __syncthreads();
        float mean[4];
        #pragma unroll
        for (int r = 0; r < 4; r++) {
            float s = 0.f;
            #pragma unroll
            for (int i = 0; i < 8; i++) s += rb[r][i];
            mean[r] = s * (1.0f/Dq);
        }
        __syncthreads();
        float d[4];
        #pragma unroll
        for (int r = 0; r < 4; r++) d[r] = hv[r] - mean[r];
        s0 = d[0]*d[0]; s1 = d[1]*d[1]; s2 = d[2]*d[2]; s3 = d[3]*d[3];
        #pragma unroll
        for (int o = 16; o > 0; o >>= 1) {
            s0 += __shfl_xor_sync(0xffffffffu, s0, o);
            s1 += __shfl_xor_sync(0xffffffffu, s1, o);
            s2 += __shfl_xor_sync(0xffffffffu, s2, o);
            s3 += __shfl_xor_sync(0xffffffffu, s3, o);
        }
        if (l == 0) { rb[0][w] = s0; rb[1][w] = s1; rb[2][w] = s2; rb[3][w] = s3; }
        __syncthreads();
        float lw = lfw[t], lb = lfb[t];
        #pragma unroll
        for (int r = 0; r < 4; r++) {
            float var = 0.f;
            #pragma unroll
            for (int i = 0; i < 8; i++) var += rb[r][i];
            var *= (1.0f/Dq);
            hl[r][t] = d[r] * rsqrtf(var + LN_EPS) * lw + lb;
        }
    }
    __syncthreads();

    {
        float fa[4] = {}, fb[4] = {};
        const float4* wa = (const float4*)(w1 + (size_t)t*Dq);
        const float4* wb = (const float4*)(w1 + (size_t)(256 + t)*Dq);
        #pragma unroll 4
        for (int k4 = 0; k4 < 64; k4++) {
            float4 w4a = wa[k4], w4b = wb[k4];
            #pragma unroll
            for (int r = 0; r < 4; r++) {
                float4 h4 = *(const float4*)&hl[r][k4*4];
                fa[r] += dot4f(w4a, h4);
                fb[r] += dot4f(w4b, h4);
            }
        }
        float b1a = b1[t], b1b = b1[256 + t];
        #pragma unroll
        for (int r = 0; r < 4; r++) {
            f1[r][t]       = fmaxf(fa[r] + b1a, 0.f);
            f1[r][256 + t] = fmaxf(fb[r] + b1b, 0.f);
        }
    }
    __syncthreads();

    float oo[4];
    {
        float o[4] = {};
        const float4* wr = (const float4*)(w2 + (size_t)t*Hq);
        #pragma unroll 4
        for (int k4 = 0; k4 < 128; k4++) {
            float4 w4 = wr[k4];
            #pragma unroll
            for (int r = 0; r < 4; r++)
                o[r] += dot4f(w4, *(const float4*)&f1[r][k4*4]);
        }
        float b2t = b2[t];
        float* dst = last ? final_out : slots;
        #pragma unroll
        for (int r = 0; r < 4; r++) {
            oo[r] = o[r] + b2t + nm[r][t];
            dst[(size_t)(r0 + r)*Dq + t] = oo[r];
        }
    }

    if (last) return;

    __syncthreads();
    {
        float s0 = oo[0], s1 = oo[1], s2 = oo[2], s3 = oo[3];
        #pragma unroll
        for (int o = 16; o > 0; o >>= 1) {
            s0 += __shfl_xor_sync(0xffffffffu, s0, o);
            s1 += __shfl_xor_sync(0xffffffffu, s1, o);
            s2 += __shfl_xor_sync(0xffffffffu, s2, o);
            s3 += __shfl_xor_sync(0xffffffffu, s3, o);
        }
        if (l == 0) { rb[0][w] = s0; rb[1][w] = s1; rb[2][w] = s2; rb[3][w] = s3; }
        __syncthreads();
        float mean[4];
        #pragma unroll
        for (int r = 0; r < 4; r++) {
            float s = 0.f;
            #pragma unroll
            for (int i = 0; i < 8; i++) s += rb[r][i];
            mean[r] = s * (1.0f/Dq);
        }
        __syncthreads();
        float d[4];
        #pragma unroll
        for (int r = 0; r < 4; r++) d[r] = oo[r] - mean[r];
        s0 = d[0]*d[0]; s1 = d[1]*d[1]; s2 = d[2]*d[2]; s3 = d[3]*d[3];
        #pragma unroll
        for (int o = 16; o > 0; o >>= 1) {
            s0 += __shfl_xor_sync(0xffffffffu, s0, o);
            s1 += __shfl_xor_sync(0xffffffffu, s1, o);
            s2 += __shfl_xor_sync(0xffffffffu, s2, o);
            s3 += __shfl_xor_sync(0xffffffffu, s3, o);
        }
        if (l == 0) { rb[0][w] = s0; rb[1][w] = s1; rb[2][w] = s2; rb[3][w] = s3; }
        __syncthreads();
        float lw = lsw[t], lb = lsb[t];
        #pragma unroll
        for (int r = 0; r < 4; r++) {
            float var = 0.f;
            #pragma unroll
            for (int i = 0; i < 8; i++) var += rb[r][i];
            var *= (1.0f/Dq);
            hl[r][t] = d[r] * rsqrtf(var + LN_EPS) * lw + lb;
        }
    }
    __syncthreads();
    {
        float q[4] = {};
        const float4* wr = (const float4*)(w2t + (size_t)t*Dq);
        #pragma unroll 4
        for (int k4 = 0; k4 < 64; k4++) {
            float4 w4 = wr[k4];
            #pragma unroll
            for (int r = 0; r < 4; r++)
                q[r] += dot4f(w4, *(const float4*)&hl[r][k4*4]);
        }
        float bq_t = bqk[t];
        #pragma unroll
        for (int r = 0; r < 4; r++)
            qk_out[(size_t)(r0 + r)*Dq + t] = q[r] + bq_t;
    }
    {
        float vbt = vb[t];
        float s0 = hl[0][t]*vbt, s1 = hl[1][t]*vbt, s2 = hl[2][t]*vbt, s3 = hl[3][t]*vbt;
        #pragma unroll
        for (int o = 16; o > 0; o >>= 1) {
            s0 += __shfl_xor_sync(0xffffffffu, s0, o);
            s1 += __shfl_xor_sync(0xffffffffu, s1, o);
            s2 += __shfl_xor_sync(0xffffffffu, s2, o);
            s3 += __shfl_xor_sync(0xffffffffu, s3, o);
        }
        if (l == 0) { rb[0][w] = s0; rb[1][w] = s1; rb[2][w] = s2; rb[3][w] = s3; }
        __syncthreads();
        if (t < 4) {
            float s = 0.f;
            #pragma unroll
            for (int i = 0; i < 8; i++) s += rb[t][i];
            c_out[r0 + t] = s + cconst[0];
        }
    }
}

// -------------------- host --------------------
extern "C" void kernel_launch(void* const* d_in, const int* in_sizes, int n_in,
                              void* d_out, int out_size) {
    (void)in_sizes; (void)n_in; (void)out_size;
    const float* inputs    = (const float*)d_in[0];
    const float* query_pos = (const float*)d_in[1];
    const float* wq   = (const float*)d_in[2];
    const float* bq   = (const float*)d_in[3];
    const float* wk   = (const float*)d_in[4];
    const float* bk   = (const float*)d_in[5];
    const float* wv   = (const float*)d_in[6];
    const float* bv   = (const float*)d_in[7];
    const float* w_ih = (const float*)d_in[8];
    const float* b_ih = (const float*)d_in[9];
    const float* w_hh = (const float*)d_in[10];
    const float* b_hh = (const float*)d_in[11];
    const float* w1   = (const float*)d_in[12];
    const float* b1   = (const float*)d_in[13];
    const float* w2   = (const float*)d_in[14];
    const float* b2   = (const float*)d_in[15];
    const float* ln_in_w = (const float*)d_in[16];
    const float* ln_in_b = (const float*)d_in[17];
    const float* ln_s_w  = (const float*)d_in[18];
    const float* ln_s_b  = (const float*)d_in[19];
    const float* ln_ff_w = (const float*)d_in[20];
    const float* ln_ff_b = (const float*)d_in[21];
    float* out = (float*)d_out;

    float *xln, *slots, *s, *qkb, *c, *part, *dpart, *w2t, *vb, *bqk, *cconst;
    cudaGetSymbolAddress((void**)&xln,   g_xln);
    cudaGetSymbolAddress((void**)&slots, g_slots);
    cudaGetSymbolAddress((void**)&s,     g_s);
    cudaGetSymbolAddress((void**)&qkb,   g_qk);
    cudaGetSymbolAddress((void**)&c,     g_c);
    cudaGetSymbolAddress((void**)&part,  g_part);
    cudaGetSymbolAddress((void**)&dpart, g_dpart);
    cudaGetSymbolAddress((void**)&w2t,   g_w2t);
    cudaGetSymbolAddress((void**)&vb,    g_vb);
    cudaGetSymbolAddress((void**)&bqk,   g_bqk);
    cudaGetSymbolAddress((void**)&cconst,g_cconst);

    // once
    ln_rows_kernel<<<Bq*Nq, 256>>>(inputs, ln_in_w, ln_in_b, xln);
    init_slots_kernel<<<ROWS, 256>>>(query_pos, slots);
    prep_w2_kernel<<<dim3(4, 4), 256>>>(wq, wk, w2t);
    prep_small2_kernel<<<16, 256>>>(wq, wk, bq, bk, vb, bqk, cconst);
    // iter-0 prologue: s = LN(slots), c, qk
    lncv_kernel<<<ROWS, 256>>>(slots, ln_s_w, ln_s_b, vb, cconst, s, c);
    gemm64_kernel<<<dim3(4, 8), 256>>>(s, w2t, bqk, qkb, Dq, Dq);

    for (int it = 0; it < 4; it++) {
        int last = (it == 3);
        attend3_kernel<<<dim3(ACH, Bq), 256>>>(xln, qkb, c, part, dpart);
        epilogue_kernel<<<ROWS/4, 256>>>(part, dpart, slots,
                                         wv, bv, w_ih, b_ih, w_hh, b_hh,
                                         w1, b1, w2, b2,
                                         ln_ff_w, ln_ff_b, ln_s_w, ln_s_b,
                                         vb, cconst, w2t, bqk,
                                         qkb, c, out, last);
    }
}

// round 14
// speedup vs baseline: 1.1181x; 1.1181x over previous
#include <cuda_runtime.h>
#include <cuda_bf16.h>
#include <math.h>

#define Bq 64
#define Nq 4096
#define Dq 256
#define Hq 512
#define ROWS 512
#define SCALEF 0.0625f
#define LN_EPS 1e-5f
#define EPS_A 1e-8f

#define TPW 2                 // tokens per warp (attend4)
#define TILE_TOK 16           // tokens per block-tile (8 warps * 2)
#define ATPB 16               // tiles per block -> 256 tokens/block
#define ACH (Nq/(TILE_TOK*ATPB))   // 16 chunks per batch

// -------------------- scratch --------------------
__device__ float g_xln[(size_t)Bq*Nq*Dq];
__device__ float g_slots[ROWS*Dq];
__device__ float g_s[ROWS*Dq];
__device__ float g_qk[ROWS*Dq];
__device__ float g_c[ROWS];
__device__ float g_numer[ROWS*Dq];
__device__ float g_part[(size_t)ACH*ROWS*Dq];
__device__ float g_dpart[ACH*ROWS];
__device__ float g_upd[ROWS*Dq];
__device__ float g_gx[ROWS*3*Dq];
__device__ float g_gh[ROWS*3*Dq];
__device__ float g_h[ROWS*Dq];
__device__ float g_hln[ROWS*Dq];
__device__ float g_ff1[ROWS*Hq];
__device__ float g_w2t[Dq*Dq];
__device__ float g_vb[Dq];
__device__ float g_bqk[Dq];
__device__ float g_cconst[1];

// -------------------- LayerNorm rows of 256 --------------------
__global__ void ln_rows_kernel(const float* __restrict__ x, const float* __restrict__ w,
                               const float* __restrict__ bb, float* __restrict__ y) {
    __shared__ float sm[8];
    __shared__ float sm2[8];
    size_t row = blockIdx.x;
    int t = threadIdx.x;
    float v = x[row*Dq + t];
    float s = v;
    #pragma unroll
    for (int o = 16; o > 0; o >>= 1) s += __shfl_xor_sync(0xffffffffu, s, o);
    if ((t & 31) == 0) sm[t >> 5] = s;
    __syncthreads();
    float mean = 0.f;
    #pragma unroll
    for (int i = 0; i < 8; i++) mean += sm[i];
    mean *= (1.0f/Dq);
    float d = v - mean;
    float sq = d*d;
    #pragma unroll
    for (int o = 16; o > 0; o >>= 1) sq += __shfl_xor_sync(0xffffffffu, sq, o);
    if ((t & 31) == 0) sm2[t >> 5] = sq;
    __syncthreads();
    float var = 0.f;
    #pragma unroll
    for (int i = 0; i < 8; i++) var += sm2[i];
    var *= (1.0f/Dq);
    y[row*Dq + t] = d * rsqrtf(var + LN_EPS) * w[t] + bb[t];
}

// -------------------- LN(slots) fused with c = s.vb + cconst --------------------
__global__ void lncv_kernel(const float* __restrict__ x, const float* __restrict__ w,
                            const float* __restrict__ bb, const float* __restrict__ vb,
                            const float* __restrict__ cconst,
                            float* __restrict__ y, float* __restrict__ c) {
    __shared__ float sm[8];
    __shared__ float sm2[8];
    __shared__ float sm3[8];
    size_t row = blockIdx.x;
    int t = threadIdx.x;
    float v = x[row*Dq + t];
    float s = v;
    #pragma unroll
    for (int o = 16; o > 0; o >>= 1) s += __shfl_xor_sync(0xffffffffu, s, o);
    if ((t & 31) == 0) sm[t >> 5] = s;
    __syncthreads();
    float mean = 0.f;
    #pragma unroll
    for (int i = 0; i < 8; i++) mean += sm[i];
    mean *= (1.0f/Dq);
    float d = v - mean;
    float sq = d*d;
    #pragma unroll
    for (int o = 16; o > 0; o >>= 1) sq += __shfl_xor_sync(0xffffffffu, sq, o);
    if ((t & 31) == 0) sm2[t >> 5] = sq;
    __syncthreads();
    float var = 0.f;
    #pragma unroll
    for (int i = 0; i < 8; i++) var += sm2[i];
    var *= (1.0f/Dq);
    float out = d * rsqrtf(var + LN_EPS) * w[t] + bb[t];
    y[row*Dq + t] = out;
    float p = out * vb[t];
    #pragma unroll
    for (int o = 16; o > 0; o >>= 1) p += __shfl_xor_sync(0xffffffffu, p, o);
    if ((t & 31) == 0) sm3[t >> 5] = p;
    __syncthreads();
    if (t == 0) {
        float sum = 0.f;
        #pragma unroll
        for (int i = 0; i < 8; i++) sum += sm3[i];
        c[row] = sum + cconst[0];
    }
}

__global__ void init_slots_kernel(const float* __restrict__ qp, float* __restrict__ slots) {
    int row = blockIdx.x, d = threadIdx.x;
    slots[row*Dq + d] = qp[(row & 7)*Dq + d];
}

// -------------------- precompute W2T = SCALE*(wq.T@wk) [n][k] --------------------
__global__ void __launch_bounds__(256) prep_w2_kernel(const float* __restrict__ wq,
                                                      const float* __restrict__ wk,
                                                      float* __restrict__ w2t) {
    __shared__ float As[64][68];
    __shared__ float Bs[64][68];
    int n0 = blockIdx.y * 64, m0 = blockIdx.x * 64;
    int t = threadIdx.x, tx = t & 15, ty = t >> 4;
    float acc[4][4] = {};
    for (int e0 = 0; e0 < Dq; e0 += 64) {
        #pragma unroll
        for (int i = 0; i < 4; i++) {
            int f4 = t + i*256;
            int r = f4 >> 4, cq = f4 & 15;
            float4 va = *(const float4*)(wq + (size_t)(e0 + r)*Dq + m0 + 4*cq);
            *(float4*)&As[r][4*cq] = va;
            float4 vb4 = *(const float4*)(wk + (size_t)(e0 + r)*Dq + n0 + 4*cq);
            *(float4*)&Bs[r][4*cq] = vb4;
        }
        __syncthreads();
        #pragma unroll
        for (int kk = 0; kk < 64; kk++) {
            float nv[4], mv[4];
            #pragma unroll
            for (int i = 0; i < 4; i++) nv[i] = Bs[kk][4*ty + i];
            #pragma unroll
            for (int j = 0; j < 4; j++) mv[j] = As[kk][4*tx + j];
            #pragma unroll
            for (int i = 0; i < 4; i++)
                #pragma unroll
                for (int j = 0; j < 4; j++)
                    acc[i][j] = fmaf(nv[i], mv[j], acc[i][j]);
        }
        __syncthreads();
    }
    #pragma unroll
    for (int i = 0; i < 4; i++)
        #pragma unroll
        for (int j = 0; j < 4; j++)
            w2t[(size_t)(n0 + 4*ty + i)*Dq + m0 + 4*tx + j] = SCALEF * acc[i][j];
}

// -------------------- precompute vb, bqk, cconst --------------------
__global__ void prep_small2_kernel(const float* __restrict__ wq, const float* __restrict__ wk,
                                   const float* __restrict__ bq, const float* __restrict__ bk,
                                   float* __restrict__ vb, float* __restrict__ bqk,
                                   float* __restrict__ cconst) {
    __shared__ float red[8][33];
    int blk = blockIdx.x;
    int t = threadIdx.x;
    int to = t & 31, eg = t >> 5;
    bool isB = blk >= 8;
    int t0 = (blk & 7)*32 + to;
    float p = 0.f;
    #pragma unroll 4
    for (int e = eg*32; e < eg*32 + 32; e++) {
        p = isB ? fmaf(bq[e], wk[(size_t)e*Dq + t0], p)
                : fmaf(wq[(size_t)e*Dq + t0], bk[e], p);
    }
    red[eg][to] = p;
    __syncthreads();
    if (t < 32) {
        float s = 0.f;
        #pragma unroll
        for (int i = 0; i < 8; i++) s += red[i][t];
        (isB ? bqk : vb)[(blk & 7)*32 + t] = SCALEF * s;
    }
    if (blk == 0) {
        __syncthreads();
        float q = bq[t]*bk[t];
        #pragma unroll
        for (int o = 16; o > 0; o >>= 1) q += __shfl_xor_sync(0xffffffffu, q, o);
        if ((t & 31) == 0) red[0][t >> 5] = q;
        __syncthreads();
        if (t == 0) {
            float s = 0.f;
            #pragma unroll
            for (int i = 0; i < 8; i++) s += red[0][i];
            cconst[0] = SCALEF * s;
        }
    }
}

// -------------------- GEMM 64x64, BK=64: C = act(A@W^T + bias)(+res) --------------
template<bool RELU>
__device__ __forceinline__ void gemm64_body(const float* __restrict__ A,
                                            const float* __restrict__ W,
                                            const float* __restrict__ bias,
                                            const float* __restrict__ res,
                                            float* __restrict__ C,
                                            int N, int K, int m0, int n0) {
    __shared__ float As[64][65];
    __shared__ float Bs[64][65];
    int t = threadIdx.x, tx = t & 15, ty = t >> 4;
    float acc[4][4] = {};
    for (int k0 = 0; k0 < K; k0 += 64) {
        #pragma unroll
        for (int i = 0; i < 4; i++) {
            int f4 = t + i*256;
            int r = f4 >> 4, kq = f4 & 15;
            float4 va = *(const float4*)(A + (size_t)(m0 + r)*K + k0 + 4*kq);
            As[r][4*kq + 0] = va.x; As[r][4*kq + 1] = va.y;
            As[r][4*kq + 2] = va.z; As[r][4*kq + 3] = va.w;
            float4 vb4 = *(const float4*)(W + (size_t)(n0 + r)*K + k0 + 4*kq);
            Bs[r][4*kq + 0] = vb4.x; Bs[r][4*kq + 1] = vb4.y;
            Bs[r][4*kq + 2] = vb4.z; Bs[r][4*kq + 3] = vb4.w;
        }
        __syncthreads();
        #pragma unroll
        for (int kk = 0; kk < 64; kk++) {
            float a[4], b[4];
            #pragma unroll
            for (int i = 0; i < 4; i++) a[i] = As[4*ty + i][kk];
            #pragma unroll
            for (int j = 0; j < 4; j++) b[j] = Bs[4*tx + j][kk];
            #pragma unroll
            for (int i = 0; i < 4; i++)
                #pragma unroll
                for (int j = 0; j < 4; j++)
                    acc[i][j] = fmaf(a[i], b[j], acc[i][j]);
        }
        __syncthreads();
    }
    #pragma unroll
    for (int i = 0; i < 4; i++) {
        int m = m0 + 4*ty + i;
        #pragma unroll
        for (int j = 0; j < 4; j++) {
            int n = n0 + 4*tx + j;
            float v = acc[i][j];
            if (bias) v += bias[n];
            if (RELU) v = fmaxf(v, 0.f);
            if (res)  v += res[(size_t)m*N + n];
            C[(size_t)m*N + n] = v;
        }
    }
}

template<bool RELU>
__global__ void __launch_bounds__(256) gemm64_kernel(const float* __restrict__ A,
                                                     const float* __restrict__ W,
                                                     const float* __restrict__ bias,
                                                     const float* __restrict__ res,
                                                     float* __restrict__ C,
                                                     int N, int K) {
    gemm64_body<RELU>(A, W, bias, res, C, N, K, blockIdx.y*64, blockIdx.x*64);
}

__global__ void __launch_bounds__(256) gemm64_dual_kernel(const float* __restrict__ A0,
                                                          const float* __restrict__ W0,
                                                          const float* __restrict__ b0,
                                                          float* __restrict__ C0,
                                                          const float* __restrict__ A1,
                                                          const float* __restrict__ W1,
                                                          const float* __restrict__ b1,
                                                          float* __restrict__ C1,
                                                          int N, int K) {
    if (blockIdx.z == 0)
        gemm64_body<false>(A0, W0, b0, nullptr, C0, N, K, blockIdx.y*64, blockIdx.x*64);
    else
        gemm64_body<false>(A1, W1, b1, nullptr, C1, N, K, blockIdx.y*64, blockIdx.x*64);
}

// -------------------- attend v4: TPW=2, <=128 regs, 2 CTAs/SM --------------------
__global__ void __launch_bounds__(256, 2) attend4_kernel(const float* __restrict__ xln,
                                                         const float* __restrict__ qk,
                                                         const float* __restrict__ cc,
                                                         float* __restrict__ part,
                                                         float* __restrict__ dpart) {
    __shared__ float4 qk4[512];            // [s][64] float4 view of qk[b]
    __shared__ float red[2048];            // [s][256] block partial numer
    __shared__ float sds[64];              // [warp][slot] partial denom
    __shared__ __align__(16) float a_sh[8][16];  // per-warp weights: 16 (tok,slot)
    int b = blockIdx.y;
    int t = threadIdx.x, w = t >> 5, l = t & 31;
    {
        const float4* src = (const float4*)(qk + (size_t)b*8*Dq);
        qk4[t]       = src[t];
        qk4[t + 256] = src[t + 256];
    }
    float cr = cc[b*8 + (l & 7)];
    #pragma unroll
    for (int i = 0; i < 8; i++) red[t + i*256] = 0.f;
    __syncthreads();

    float accB[64];
    #pragma unroll
    for (int i = 0; i < 64; i++) accB[i] = 0.f;
    float dsl = 0.f;

    const float* xp0 = xln + ((size_t)b*Nq + (size_t)blockIdx.x*(TILE_TOK*ATPB) + w*TPW)*Dq;

    for (int tile = 0; tile < ATPB; tile++) {
        const float* xp = xp0 + (size_t)tile*TILE_TOK*Dq;
        float4 xa[TPW], xb[TPW];
        #pragma unroll
        for (int j = 0; j < TPW; j++) {
            xa[j] = *(const float4*)(xp + j*Dq + 4*l);
            xb[j] = *(const float4*)(xp + j*Dq + 128 + 4*l);
        }
        // phase A: 16 (tok,slot) partial logits per lane
        float v[16];
        #pragma unroll
        for (int s = 0; s < 8; s++) {
            float4 qa = qk4[s*64 + l];
            float4 qb = qk4[s*64 + 32 + l];
            #pragma unroll
            for (int j = 0; j < TPW; j++) {
                float p = xa[j].x * qa.x;
                p = fmaf(xa[j].y, qa.y, p);
                p = fmaf(xa[j].z, qa.z, p);
                p = fmaf(xa[j].w, qa.w, p);
                p = fmaf(xb[j].x, qb.x, p);
                p = fmaf(xb[j].y, qb.y, p);
                p = fmaf(xb[j].z, qb.z, p);
                p = fmaf(xb[j].w, qb.w, p);
                v[j*8 + s] = p;
            }
        }
        // combine the two 16-lane halves (duplicated afterwards)
        #pragma unroll
        for (int i = 0; i < 16; i++)
            v[i] += __shfl_xor_sync(0xffffffffu, v[i], 16);
        // swap-reduce within 16-lane halves: lane ends with entry (l&15)
        #pragma unroll
        for (int half = 8; half >= 1; half >>= 1) {
            int hi = l & half;
            #pragma unroll
            for (int i = 0; i < half; i++) {
                float send = hi ? v[i] : v[i + half];
                float keep = hi ? v[i + half] : v[i];
                v[i] = keep + __shfl_xor_sync(0xffffffffu, send, half);
            }
        }
        // softmax over the 8-lane slot group (entry tok=(l>>3)&1, slot=l&7)
        float lg = v[0] + cr;
        float m = lg;
        #pragma unroll
        for (int o = 1; o <= 4; o <<= 1) m = fmaxf(m, __shfl_xor_sync(0xffffffffu, m, o));
        float e = __expf(lg - m);
        float sum = e;
        #pragma unroll
        for (int o = 1; o <= 4; o <<= 1) sum += __shfl_xor_sync(0xffffffffu, sum, o);
        float a = fmaf(e, __fdividef(1.f, sum), EPS_A);
        dsl += a;
        __syncwarp();
        if (l < 16) a_sh[w][l] = a;
        __syncwarp();
        // phase B: rank-accumulate numer partials
        #pragma unroll
        for (int j = 0; j < TPW; j++) {
            float4 a0 = *(const float4*)&a_sh[w][j*8];
            float4 a1 = *(const float4*)&a_sh[w][j*8 + 4];
            float av[8] = {a0.x, a0.y, a0.z, a0.w, a1.x, a1.y, a1.z, a1.w};
            #pragma unroll
            for (int s = 0; s < 8; s++) {
                accB[s*8 + 0] = fmaf(av[s], xa[j].x, accB[s*8 + 0]);
                accB[s*8 + 1] = fmaf(av[s], xa[j].y, accB[s*8 + 1]);
                accB[s*8 + 2] = fmaf(av[s], xa[j].z, accB[s*8 + 2]);
                accB[s*8 + 3] = fmaf(av[s], xa[j].w, accB[s*8 + 3]);
                accB[s*8 + 4] = fmaf(av[s], xb[j].x, accB[s*8 + 4]);
                accB[s*8 + 5] = fmaf(av[s], xb[j].y, accB[s*8 + 5]);
                accB[s*8 + 6] = fmaf(av[s], xb[j].z, accB[s*8 + 6]);
                accB[s*8 + 7] = fmaf(av[s], xb[j].w, accB[s*8 + 7]);
            }
        }
    }
    // denom: halves are duplicates; xor-8 combines the two tokens
    dsl += __shfl_xor_sync(0xffffffffu, dsl, 8);
    if (l < 8) sds[w*8 + l] = dsl;
    // cross-warp reduce accB into red (serialized rounds, deterministic)
    for (int r = 0; r < 8; r++) {
        __syncthreads();
        if (w == r) {
            #pragma unroll
            for (int s = 0; s < 8; s++) {
                #pragma unroll
                for (int q = 0; q < 4; q++) {
                    red[s*256 + 4*l + q]       += accB[s*8 + q];
                    red[s*256 + 128 + 4*l + q] += accB[s*8 + 4 + q];
                }
            }
        }
    }
    __syncthreads();
    size_t pbase = ((size_t)blockIdx.x*ROWS + b*8)*Dq;
    #pragma unroll
    for (int i = 0; i < 8; i++) part[pbase + i*256 + t] = red[i*256 + t];
    if (t < 8) {
        float sum = 0.f;
        #pragma unroll
        for (int ww = 0; ww < 8; ww++) sum += sds[ww*8 + t];
        dpart[blockIdx.x*ROWS + b*8 + t] = sum;
    }
}

// -------------------- reduce partials over chunks and normalize --------------------
__global__ void reduce_norm_kernel(const float* __restrict__ part,
                                   const float* __restrict__ dpart,
                                   float* __restrict__ numer) {
    int row = blockIdx.x, t = threadIdx.x;
    float s = 0.f, dn = 0.f;
    #pragma unroll
    for (int c = 0; c < ACH; c++) {
        s  += part[((size_t)c*ROWS + row)*Dq + t];
        dn += dpart[c*ROWS + row];
    }
    numer[(size_t)row*Dq + t] = s / dn;
}

// -------------------- GRU cell fused with LN_ff --------------------
__global__ void gruln_kernel(const float* __restrict__ gx, const float* __restrict__ gh,
                             const float* __restrict__ slots,
                             const float* __restrict__ lw, const float* __restrict__ lb,
                             float* __restrict__ h, float* __restrict__ hln) {
    __shared__ float sm[8];
    __shared__ float sm2[8];
    int row = blockIdx.x, t = threadIdx.x;
    const float* gxr = gx + (size_t)row*768;
    const float* ghr = gh + (size_t)row*768;
    float r = 1.f/(1.f + expf(-(gxr[t]       + ghr[t])));
    float z = 1.f/(1.f + expf(-(gxr[256 + t] + ghr[256 + t])));
    float n = tanhf(gxr[512 + t] + r*ghr[512 + t]);
    float hv = (1.f - z)*n + z*slots[(size_t)row*Dq + t];
    h[(size_t)row*Dq + t] = hv;
    float s = hv;
    #pragma unroll
    for (int o = 16; o > 0; o >>= 1) s += __shfl_xor_sync(0xffffffffu, s, o);
    if ((t & 31) == 0) sm[t >> 5] = s;
    __syncthreads();
    float mean = 0.f;
    #pragma unroll
    for (int i = 0; i < 8; i++) mean += sm[i];
    mean *= (1.0f/Dq);
    float d = hv - mean;
    float sq = d*d;
    #pragma unroll
    for (int o = 16; o > 0; o >>= 1) sq += __shfl_xor_sync(0xffffffffu, sq, o);
    if ((t & 31) == 0) sm2[t >> 5] = sq;
    __syncthreads();
    float var = 0.f;
    #pragma unroll
    for (int i = 0; i < 8; i++) var += sm2[i];
    var *= (1.0f/Dq);
    hln[(size_t)row*Dq + t] = d * rsqrtf(var + LN_EPS) * lw[t] + lb[t];
}

// -------------------- host --------------------
extern "C" void kernel_launch(void* const* d_in, const int* in_sizes, int n_in,
                              void* d_out, int out_size) {
    (void)in_sizes; (void)n_in; (void)out_size;
    const float* inputs    = (const float*)d_in[0];
    const float* query_pos = (const float*)d_in[1];
    const float* wq   = (const float*)d_in[2];
    const float* bq   = (const float*)d_in[3];
    const float* wk   = (const float*)d_in[4];
    const float* bk   = (const float*)d_in[5];
    const float* wv   = (const float*)d_in[6];
    const float* bv   = (const float*)d_in[7];
    const float* w_ih = (const float*)d_in[8];
    const float* b_ih = (const float*)d_in[9];
    const float* w_hh = (const float*)d_in[10];
    const float* b_hh = (const float*)d_in[11];
    const float* w1   = (const float*)d_in[12];
    const float* b1   = (const float*)d_in[13];
    const float* w2   = (const float*)d_in[14];
    const float* b2   = (const float*)d_in[15];
    const float* ln_in_w = (const float*)d_in[16];
    const float* ln_in_b = (const float*)d_in[17];
    const float* ln_s_w  = (const float*)d_in[18];
    const float* ln_s_b  = (const float*)d_in[19];
    const float* ln_ff_w = (const float*)d_in[20];
    const float* ln_ff_b = (const float*)d_in[21];
    float* out = (float*)d_out;

    float *xln, *slots, *s, *qkb, *c, *numer, *part, *dpart, *upd, *gx, *gh, *h, *hln, *ff1;
    float *w2t, *vb, *bqk, *cconst;
    cudaGetSymbolAddress((void**)&xln,   g_xln);
    cudaGetSymbolAddress((void**)&slots, g_slots);
    cudaGetSymbolAddress((void**)&s,     g_s);
    cudaGetSymbolAddress((void**)&qkb,   g_qk);
    cudaGetSymbolAddress((void**)&c,     g_c);
    cudaGetSymbolAddress((void**)&numer, g_numer);
    cudaGetSymbolAddress((void**)&part,  g_part);
    cudaGetSymbolAddress((void**)&dpart, g_dpart);
    cudaGetSymbolAddress((void**)&upd,   g_upd);
    cudaGetSymbolAddress((void**)&gx,    g_gx);
    cudaGetSymbolAddress((void**)&gh,    g_gh);
    cudaGetSymbolAddress((void**)&h,     g_h);
    cudaGetSymbolAddress((void**)&hln,   g_hln);
    cudaGetSymbolAddress((void**)&ff1,   g_ff1);
    cudaGetSymbolAddress((void**)&w2t,   g_w2t);
    cudaGetSymbolAddress((void**)&vb,    g_vb);
    cudaGetSymbolAddress((void**)&bqk,   g_bqk);
    cudaGetSymbolAddress((void**)&cconst,g_cconst);

    // once per launch
    ln_rows_kernel<<<Bq*Nq, 256>>>(inputs, ln_in_w, ln_in_b, xln);
    init_slots_kernel<<<ROWS, 256>>>(query_pos, slots);
    prep_w2_kernel<<<dim3(4, 4), 256>>>(wq, wk, w2t);
    prep_small2_kernel<<<16, 256>>>(wq, wk, bq, bk, vb, bqk, cconst);

    for (int it = 0; it < 4; it++) {
        float* slots_out = (it == 3) ? out : slots;
        lncv_kernel<<<ROWS, 256>>>(slots, ln_s_w, ln_s_b, vb, cconst, s, c);
        gemm64_kernel<false><<<dim3(4, 8), 256>>>(s, w2t, bqk, nullptr, qkb, Dq, Dq);
        attend4_kernel<<<dim3(ACH, Bq), 256>>>(xln, qkb, c, part, dpart);
        reduce_norm_kernel<<<ROWS, 256>>>(part, dpart, numer);
        gemm64_kernel<false><<<dim3(4, 8), 256>>>(numer, wv, bv, nullptr, upd, Dq, Dq);
        gemm64_dual_kernel<<<dim3(12, 8, 2), 256>>>(upd, w_ih, b_ih, gx,
                                                    slots, w_hh, b_hh, gh, 3*Dq, Dq);
        gruln_kernel<<<ROWS, 256>>>(gx, gh, slots, ln_ff_w, ln_ff_b, h, hln);
        gemm64_kernel<true ><<<dim3(8, 8), 256>>>(hln, w1, b1, nullptr, ff1, Hq, Dq);
        gemm64_kernel<false><<<dim3(4, 8), 256>>>(ff1, w2, b2, h, slots_out, Dq, Hq);
    }
}